// round 4
// baseline (speedup 1.0000x reference)
#include <cuda_runtime.h>
#include <cuda_bf16.h>
#include <math.h>

#define MAX_NODES 1000000

// Pre-scaled nodal displacement: {ux*u_c, uy*u_c, th*theta_c, 0}
__device__ float4 g_pred4[MAX_NODES];
// Accumulator: starts at {-Fe_x, -Fe_y, -Fe_z, packed_masks}; elements add
// their forces (w += 0.0f), so after elem pass it holds {R_x, R_y, R_z, masks}.
__device__ float4 g_Fint4[MAX_NODES];
__device__ double g_acc[2];     // [0] = sum(R_free^2), [1] = sum(F_free^2)
__device__ unsigned g_done;     // last-block ticket for node_kernel

// ---------------------------------------------------------------------------
// Kernel 1: prep — 4 nodes/thread, float4 I/O.
//   g_pred4[i] = scaled displacement
//   g_Fint4[i] = {-F_ext, md + 2*mr}
//   g_acc[1]  += sum(F_free^2)   (complete after this kernel)
// ---------------------------------------------------------------------------
__global__ void __launch_bounds__(256)
prep_kernel(const float4* __restrict__ pred4,   // pred_raw as float4 (3N/4)
            const float4* __restrict__ fext4,   // F_ext   as float4 (3N/4)
            const float4* __restrict__ bcd4,    // bc_disp as float4 (N/4)
            const float4* __restrict__ bcr4,    // bc_rot  as float4 (N/4)
            const float* __restrict__ u_c,
            const float* __restrict__ theta_c,
            int N)
{
    int t = blockIdx.x * blockDim.x + threadIdx.x;   // handles nodes 4t..4t+3
    int nquad = N >> 2;                               // N is divisible by 4

    float f2 = 0.f;
    if (t < nquad) {
        float su = __ldg(u_c);
        float st = __ldg(theta_c);

        float4 p0 = pred4[3 * t + 0];
        float4 p1 = pred4[3 * t + 1];
        float4 p2 = pred4[3 * t + 2];
        float4 e0 = fext4[3 * t + 0];
        float4 e1 = fext4[3 * t + 1];
        float4 e2 = fext4[3 * t + 2];
        float4 bd = bcd4[t];
        float4 br = bcr4[t];

        // unpack 4 nodes worth of (x,y,th)
        float px[4] = {p0.x, p0.w, p1.z, p2.y};
        float py[4] = {p0.y, p1.x, p1.w, p2.z};
        float pt[4] = {p0.z, p1.y, p2.x, p2.w};
        float fx[4] = {e0.x, e0.w, e1.z, e2.y};
        float fy[4] = {e0.y, e1.x, e1.w, e2.z};
        float fz[4] = {e0.z, e1.y, e2.x, e2.w};
        float md[4] = {1.f - bd.x, 1.f - bd.y, 1.f - bd.z, 1.f - bd.w};
        float mr[4] = {1.f - br.x, 1.f - br.y, 1.f - br.z, 1.f - br.w};

        #pragma unroll
        for (int k = 0; k < 4; ++k) {
            int node = 4 * t + k;
            g_pred4[node] = make_float4(px[k] * su, py[k] * su, pt[k] * st, 0.f);
            float w = md[k] + 2.f * mr[k];            // {0,1,2,3} exact
            g_Fint4[node] = make_float4(-fx[k], -fy[k], -fz[k], w);
            float G0 = fx[k] * md[k];
            float G1 = fy[k] * md[k];
            float G2 = fz[k] * mr[k];
            f2 += G0 * G0 + G1 * G1 + G2 * G2;
        }
    }
    if (t == 0) { g_acc[0] = 0.0; g_done = 0u; }

    // block-reduce f2 -> double atomic
    for (int off = 16; off > 0; off >>= 1)
        f2 += __shfl_down_sync(0xffffffffu, f2, off);
    __shared__ float sf[8];
    int lane = threadIdx.x & 31;
    int wid  = threadIdx.x >> 5;
    if (lane == 0) sf[wid] = f2;
    __syncthreads();
    if (wid == 0) {
        float ff = (lane < 8) ? sf[lane] : 0.f;
        for (int off = 4; off > 0; off >>= 1)
            ff += __shfl_down_sync(0xffffffffu, ff, off);
        if (lane == 0) atomicAdd(&g_acc[1], (double)ff);
    }
}

// zero g_acc[1] before prep accumulates into it (tiny kernel, 1 thread)
__global__ void zero_acc_kernel() { g_acc[1] = 0.0; }

// ---------------------------------------------------------------------------
// Kernel 2: element pass — 2 adjacent elements/thread, paired streamed loads,
// float4 gathers, v4 RED scatter
// ---------------------------------------------------------------------------
#define ETB 256          // threads per block
#define EPB (2 * ETB)    // elements per block

__device__ __forceinline__ void elem_compute(
    float c, float s, int nA, int nB, float L, float EA, float EI)
{
    float4 dA = __ldg(&g_pred4[nA]);   // {ux, uy, th_scaled, 0}
    float4 dB = __ldg(&g_pred4[nB]);

    float thA = -dA.z;
    float thB = -dB.z;

    float u_A =  c * dA.x + s * dA.y;
    float w_A = -s * dA.x + c * dA.y;
    float u_B =  c * dB.x + s * dB.y;
    float w_B = -s * dB.x + c * dB.y;

    float inv_l = 1.0f / L;
    float ea_l  = EA * inv_l;
    float ei_l  = EI * inv_l;
    float ei_l2 = ei_l * inv_l;
    float ei_l3 = ei_l2 * inv_l;

    float dw = w_A - w_B;
    float f0 = ea_l * (u_A - u_B);
    float f1 = 12.0f * ei_l3 * dw + 6.0f * ei_l2 * (thA + thB);
    float f2 = 6.0f * ei_l2 * dw + 4.0f * ei_l * thA + 2.0f * ei_l * thB;
    float f5 = 6.0f * ei_l2 * dw + 2.0f * ei_l * thA + 4.0f * ei_l * thB;

    float fAx = c * f0 - s * f1;
    float fAy = s * f0 + c * f1;

    float4* pA = &g_Fint4[nA];
    asm volatile("red.global.add.v4.f32 [%0], {%1, %2, %3, %4};"
                 :: "l"(pA), "f"(fAx), "f"(fAy), "f"(-f2), "f"(0.f)
                 : "memory");
    float4* pB = &g_Fint4[nB];
    asm volatile("red.global.add.v4.f32 [%0], {%1, %2, %3, %4};"
                 :: "l"(pB), "f"(-fAx), "f"(-fAy), "f"(-f5), "f"(0.f)
                 : "memory");
}

__global__ void __launch_bounds__(ETB)
elem_kernel(const float* __restrict__ elem_len,
            const float* __restrict__ prop_E,
            const float* __restrict__ prop_A,
            const float* __restrict__ prop_I,
            const float* __restrict__ dirs,     // [E,3]
            const int*  __restrict__ conn,      // [E,2] flat
            int E)
{
    __shared__ float sdir[3 * EPB];
    int base = blockIdx.x * EPB;

    // coalesced staging of dirs for this block's EPB elements
    int lim3 = 3 * E;
    #pragma unroll
    for (int k = 0; k < 6; ++k) {
        int t = threadIdx.x + k * ETB;
        int g = base * 3 + t;
        sdir[t] = (g < lim3) ? dirs[g] : 0.f;
    }
    __syncthreads();

    int pairidx = (base >> 1) + threadIdx.x;   // index into paired views
    int e0 = base + 2 * threadIdx.x;
    int e1 = e0 + 1;

    if (e1 < E) {
        // fast path: paired vector loads
        int4   cn = ((const int4*)conn)[pairidx];
        float2 Lp = ((const float2*)elem_len)[pairidx];
        float2 Ep = ((const float2*)prop_E)[pairidx];
        float2 Ap = ((const float2*)prop_A)[pairidx];
        float2 Ip = ((const float2*)prop_I)[pairidx];

        int s6 = 6 * threadIdx.x;
        float c0 = sdir[s6 + 0], s0 = sdir[s6 + 2];
        float c1 = sdir[s6 + 3], s1 = sdir[s6 + 5];

        elem_compute(c0, s0, cn.x, cn.y, Lp.x, Ep.x * Ap.x, Ep.x * Ip.x);
        elem_compute(c1, s1, cn.z, cn.w, Lp.y, Ep.y * Ap.y, Ep.y * Ip.y);
    } else if (e0 < E) {
        // tail: single guarded element
        int nA = conn[2 * e0 + 0];
        int nB = conn[2 * e0 + 1];
        int s6 = 6 * threadIdx.x;
        float c0 = sdir[s6 + 0], s0 = sdir[s6 + 2];
        float pe = prop_E[e0];
        elem_compute(c0, s0, nA, nB, elem_len[e0], pe * prop_A[e0], pe * prop_I[e0]);
    }
}

// ---------------------------------------------------------------------------
// Kernel 3: node pass — reads ONLY g_Fint4 (R + packed masks), reduces,
// last block writes the final scalar.
// ---------------------------------------------------------------------------
__global__ void __launch_bounds__(256)
node_kernel(float* __restrict__ out, int N)
{
    int i = blockIdx.x * blockDim.x + threadIdx.x;

    float r2 = 0.f;
    if (i < N) {
        float4 Fi = g_Fint4[i];          // {Rx, Ry, Rz, md + 2*mr}
        int iw = (int)Fi.w;
        float md = (float)(iw & 1);
        float mr = (float)(iw >> 1);
        float R0 = Fi.x * md;
        float R1 = Fi.y * md;
        float R2 = Fi.z * mr;
        r2 = R0 * R0 + R1 * R1 + R2 * R2;
    }

    for (int off = 16; off > 0; off >>= 1)
        r2 += __shfl_down_sync(0xffffffffu, r2, off);

    __shared__ float sr[8];
    int lane = threadIdx.x & 31;
    int wid  = threadIdx.x >> 5;
    if (lane == 0) sr[wid] = r2;
    __syncthreads();

    if (wid == 0) {
        float rr = (lane < 8) ? sr[lane] : 0.f;
        for (int off = 4; off > 0; off >>= 1)
            rr += __shfl_down_sync(0xffffffffu, rr, off);
        if (lane == 0) {
            atomicAdd(&g_acc[0], (double)rr);
            __threadfence();
            unsigned ticket = atomicAdd(&g_done, 1u);
            if (ticket == gridDim.x - 1) {
                double fn = g_acc[1];
                if (fn < 1e-30) fn = 1e-30;
                out[0] = (float)(g_acc[0] / fn);
            }
        }
    }
}

// ---------------------------------------------------------------------------
// Launch
// ---------------------------------------------------------------------------
extern "C" void kernel_launch(void* const* d_in, const int* in_sizes, int n_in,
                              void* d_out, int out_size)
{
    const float* pred_raw = (const float*)d_in[0];   // [N,3]
    const float* u_c      = (const float*)d_in[1];   // [1]
    const float* theta_c  = (const float*)d_in[2];   // [1]
    const float* elem_len = (const float*)d_in[3];   // [E]
    const float* prop_E   = (const float*)d_in[4];   // [E]
    const float* prop_A   = (const float*)d_in[5];   // [E]
    const float* prop_I   = (const float*)d_in[6];   // [E]
    const float* dirs     = (const float*)d_in[7];   // [E,3]
    const float* F_ext    = (const float*)d_in[8];   // [N,3]
    const float* bc_disp  = (const float*)d_in[9];   // [N,1]
    const float* bc_rot   = (const float*)d_in[10];  // [N,1]
    const int*   conn     = (const int*)d_in[11];    // [E,2]

    int N = in_sizes[0] / 3;
    int E = in_sizes[3];

    float* out = (float*)d_out;

    zero_acc_kernel<<<1, 1>>>();

    int nquad = N >> 2;
    prep_kernel<<<(nquad + 255) / 256, 256>>>(
        (const float4*)pred_raw, (const float4*)F_ext,
        (const float4*)bc_disp, (const float4*)bc_rot,
        u_c, theta_c, N);

    elem_kernel<<<(E + EPB - 1) / EPB, ETB>>>(elem_len, prop_E, prop_A, prop_I,
                                              dirs, conn, E);

    node_kernel<<<(N + 255) / 256, 256>>>(out, N);
}

// round 5
// speedup vs baseline: 1.0995x; 1.0995x over previous
#include <cuda_runtime.h>
#include <cuda_bf16.h>
#include <math.h>

#define MAX_NODES 1000000

// Pre-scaled nodal displacement: {ux*u_c, uy*u_c, th*theta_c, 0}
__device__ float4 g_pred4[MAX_NODES];
// Accumulator: starts at {-Fe_x, -Fe_y, -Fe_z, packed_masks}; elements add
// their forces (w += 0.0f), so after elem pass it holds {R_x, R_y, R_z, masks}.
__device__ float4 g_Fint4[MAX_NODES];
__device__ double g_acc[2];     // [0] = sum(R_free^2), [1] = sum(F_free^2)
__device__ unsigned g_done;     // last-block ticket for node_kernel

// ---------------------------------------------------------------------------
// Kernel 1: prep — 4 nodes/thread, float4 I/O.
// ---------------------------------------------------------------------------
__global__ void __launch_bounds__(256)
prep_kernel(const float4* __restrict__ pred4,   // pred_raw as float4 (3N/4)
            const float4* __restrict__ fext4,   // F_ext   as float4 (3N/4)
            const float4* __restrict__ bcd4,    // bc_disp as float4 (N/4)
            const float4* __restrict__ bcr4,    // bc_rot  as float4 (N/4)
            const float* __restrict__ u_c,
            const float* __restrict__ theta_c,
            int N)
{
    int t = blockIdx.x * blockDim.x + threadIdx.x;   // handles nodes 4t..4t+3
    int nquad = N >> 2;

    float f2 = 0.f;
    if (t < nquad) {
        float su = __ldg(u_c);
        float st = __ldg(theta_c);

        float4 p0 = pred4[3 * t + 0];
        float4 p1 = pred4[3 * t + 1];
        float4 p2 = pred4[3 * t + 2];
        float4 e0 = fext4[3 * t + 0];
        float4 e1 = fext4[3 * t + 1];
        float4 e2 = fext4[3 * t + 2];
        float4 bd = bcd4[t];
        float4 br = bcr4[t];

        float px[4] = {p0.x, p0.w, p1.z, p2.y};
        float py[4] = {p0.y, p1.x, p1.w, p2.z};
        float pt[4] = {p0.z, p1.y, p2.x, p2.w};
        float fx[4] = {e0.x, e0.w, e1.z, e2.y};
        float fy[4] = {e0.y, e1.x, e1.w, e2.z};
        float fz[4] = {e0.z, e1.y, e2.x, e2.w};
        float md[4] = {1.f - bd.x, 1.f - bd.y, 1.f - bd.z, 1.f - bd.w};
        float mr[4] = {1.f - br.x, 1.f - br.y, 1.f - br.z, 1.f - br.w};

        #pragma unroll
        for (int k = 0; k < 4; ++k) {
            int node = 4 * t + k;
            g_pred4[node] = make_float4(px[k] * su, py[k] * su, pt[k] * st, 0.f);
            float w = md[k] + 2.f * mr[k];            // {0,1,2,3} exact
            g_Fint4[node] = make_float4(-fx[k], -fy[k], -fz[k], w);
            float G0 = fx[k] * md[k];
            float G1 = fy[k] * md[k];
            float G2 = fz[k] * mr[k];
            f2 += G0 * G0 + G1 * G1 + G2 * G2;
        }
    }
    if (t == 0) { g_acc[0] = 0.0; g_done = 0u; }

    for (int off = 16; off > 0; off >>= 1)
        f2 += __shfl_down_sync(0xffffffffu, f2, off);
    __shared__ float sf[8];
    int lane = threadIdx.x & 31;
    int wid  = threadIdx.x >> 5;
    if (lane == 0) sf[wid] = f2;
    __syncthreads();
    if (wid == 0) {
        float ff = (lane < 8) ? sf[lane] : 0.f;
        for (int off = 4; off > 0; off >>= 1)
            ff += __shfl_down_sync(0xffffffffu, ff, off);
        if (lane == 0) atomicAdd(&g_acc[1], (double)ff);
    }
}

__global__ void zero_acc_kernel() { g_acc[1] = 0.0; }

// ---------------------------------------------------------------------------
// Kernel 2: element pass — 4 adjacent elements/thread, all-vector streamed
// loads (no smem), front-batched float4 gathers, v4 RED scatter
// ---------------------------------------------------------------------------
#define ETB 256          // threads per block
#define EPT 4            // elements per thread
#define EPB (EPT * ETB)  // elements per block

__device__ __forceinline__ void elem_force(
    float c, float s, float4 dA, float4 dB, float L, float EA, float EI,
    float& fAx, float& fAy, float& f2o, float& f5o)
{
    float thA = -dA.z;
    float thB = -dB.z;

    float u_A =  c * dA.x + s * dA.y;
    float w_A = -s * dA.x + c * dA.y;
    float u_B =  c * dB.x + s * dB.y;
    float w_B = -s * dB.x + c * dB.y;

    float inv_l = 1.0f / L;
    float ea_l  = EA * inv_l;
    float ei_l  = EI * inv_l;
    float ei_l2 = ei_l * inv_l;
    float ei_l3 = ei_l2 * inv_l;

    float dw = w_A - w_B;
    float f0 = ea_l * (u_A - u_B);
    float f1 = 12.0f * ei_l3 * dw + 6.0f * ei_l2 * (thA + thB);
    f2o = 6.0f * ei_l2 * dw + 4.0f * ei_l * thA + 2.0f * ei_l * thB;
    f5o = 6.0f * ei_l2 * dw + 2.0f * ei_l * thA + 4.0f * ei_l * thB;

    fAx = c * f0 - s * f1;
    fAy = s * f0 + c * f1;
}

__device__ __forceinline__ void red_v4(float4* p, float a, float b, float cc)
{
    asm volatile("red.global.add.v4.f32 [%0], {%1, %2, %3, %4};"
                 :: "l"(p), "f"(a), "f"(b), "f"(cc), "f"(0.f)
                 : "memory");
}

__global__ void __launch_bounds__(ETB)
elem_kernel(const float4* __restrict__ len4,    // elem_len as float4
            const float4* __restrict__ pE4,
            const float4* __restrict__ pA4,
            const float4* __restrict__ pI4,
            const float4* __restrict__ dir4,    // dirs as float4 (3E/4)
            const int4*  __restrict__ conn4,    // conn as int4 (E/2)
            int E)
{
    int t = blockIdx.x * ETB + threadIdx.x;     // handles elements 4t..4t+3
    int nquad = E >> 2;                          // E divisible by 4
    if (t >= nquad) return;

    // ---- front-batched streamed vector loads ----
    int4   cnA = conn4[2 * t + 0];   // elems 4t,4t+1: {nA0,nB0,nA1,nB1}
    int4   cnB = conn4[2 * t + 1];   // elems 4t+2,4t+3
    float4 Lq  = len4[t];
    float4 Eq  = pE4[t];
    float4 Aq  = pA4[t];
    float4 Iq  = pI4[t];
    float4 q0  = dir4[3 * t + 0];    // dirs flat [12t .. 12t+12)
    float4 q1  = dir4[3 * t + 1];
    float4 q2  = dir4[3 * t + 2];

    // ---- front-batched gathers (8 outstanding LDG.128) ----
    float4 dA0 = __ldg(&g_pred4[cnA.x]);
    float4 dB0 = __ldg(&g_pred4[cnA.y]);
    float4 dA1 = __ldg(&g_pred4[cnA.z]);
    float4 dB1 = __ldg(&g_pred4[cnA.w]);
    float4 dA2 = __ldg(&g_pred4[cnB.x]);
    float4 dB2 = __ldg(&g_pred4[cnB.y]);
    float4 dA3 = __ldg(&g_pred4[cnB.z]);
    float4 dB3 = __ldg(&g_pred4[cnB.w]);

    // dirs unpack: c_k = f[3k], s_k = f[3k+2] within the 12-float slice
    float c0 = q0.x, s0 = q0.z;
    float c1 = q0.w, s1 = q1.y;
    float c2 = q1.z, s2 = q2.x;
    float c3 = q2.y, s3 = q2.w;

    float fAx, fAy, f2, f5;

    elem_force(c0, s0, dA0, dB0, Lq.x, Eq.x * Aq.x, Eq.x * Iq.x, fAx, fAy, f2, f5);
    red_v4(&g_Fint4[cnA.x],  fAx,  fAy, -f2);
    red_v4(&g_Fint4[cnA.y], -fAx, -fAy, -f5);

    elem_force(c1, s1, dA1, dB1, Lq.y, Eq.y * Aq.y, Eq.y * Iq.y, fAx, fAy, f2, f5);
    red_v4(&g_Fint4[cnA.z],  fAx,  fAy, -f2);
    red_v4(&g_Fint4[cnA.w], -fAx, -fAy, -f5);

    elem_force(c2, s2, dA2, dB2, Lq.z, Eq.z * Aq.z, Eq.z * Iq.z, fAx, fAy, f2, f5);
    red_v4(&g_Fint4[cnB.x],  fAx,  fAy, -f2);
    red_v4(&g_Fint4[cnB.y], -fAx, -fAy, -f5);

    elem_force(c3, s3, dA3, dB3, Lq.w, Eq.w * Aq.w, Eq.w * Iq.w, fAx, fAy, f2, f5);
    red_v4(&g_Fint4[cnB.z],  fAx,  fAy, -f2);
    red_v4(&g_Fint4[cnB.w], -fAx, -fAy, -f5);
}

// tail kernel for E not divisible by 4 (usually empty grid)
__global__ void elem_tail_kernel(const float* __restrict__ elem_len,
                                 const float* __restrict__ prop_E,
                                 const float* __restrict__ prop_A,
                                 const float* __restrict__ prop_I,
                                 const float* __restrict__ dirs,
                                 const int*  __restrict__ conn,
                                 int start, int E)
{
    int e = start + blockIdx.x * blockDim.x + threadIdx.x;
    if (e >= E) return;
    int nA = conn[2 * e + 0];
    int nB = conn[2 * e + 1];
    float c = dirs[3 * e + 0];
    float s = dirs[3 * e + 2];
    float pe = prop_E[e];
    float4 dA = __ldg(&g_pred4[nA]);
    float4 dB = __ldg(&g_pred4[nB]);
    float fAx, fAy, f2, f5;
    elem_force(c, s, dA, dB, elem_len[e], pe * prop_A[e], pe * prop_I[e],
               fAx, fAy, f2, f5);
    red_v4(&g_Fint4[nA],  fAx,  fAy, -f2);
    red_v4(&g_Fint4[nB], -fAx, -fAy, -f5);
}

// ---------------------------------------------------------------------------
// Kernel 3: node pass — 4 nodes/thread, batched loads, fused final divide
// ---------------------------------------------------------------------------
__global__ void __launch_bounds__(256)
node_kernel(float* __restrict__ out, int N)
{
    int t = blockIdx.x * blockDim.x + threadIdx.x;   // nodes 4t..4t+3
    int nquad = N >> 2;

    float r2 = 0.f;
    if (t < nquad) {
        float4 a = g_Fint4[4 * t + 0];
        float4 b = g_Fint4[4 * t + 1];
        float4 c = g_Fint4[4 * t + 2];
        float4 d = g_Fint4[4 * t + 3];

        #pragma unroll
        for (int k = 0; k < 4; ++k) {
            float4 Fi = (k == 0) ? a : (k == 1) ? b : (k == 2) ? c : d;
            int iw = (int)Fi.w;
            float md = (float)(iw & 1);
            float mr = (float)(iw >> 1);
            float R0 = Fi.x * md;
            float R1 = Fi.y * md;
            float R2 = Fi.z * mr;
            r2 += R0 * R0 + R1 * R1 + R2 * R2;
        }
    }

    for (int off = 16; off > 0; off >>= 1)
        r2 += __shfl_down_sync(0xffffffffu, r2, off);

    __shared__ float sr[8];
    int lane = threadIdx.x & 31;
    int wid  = threadIdx.x >> 5;
    if (lane == 0) sr[wid] = r2;
    __syncthreads();

    if (wid == 0) {
        float rr = (lane < 8) ? sr[lane] : 0.f;
        for (int off = 4; off > 0; off >>= 1)
            rr += __shfl_down_sync(0xffffffffu, rr, off);
        if (lane == 0) {
            atomicAdd(&g_acc[0], (double)rr);
            __threadfence();
            unsigned ticket = atomicAdd(&g_done, 1u);
            if (ticket == gridDim.x - 1) {
                double fn = g_acc[1];
                if (fn < 1e-30) fn = 1e-30;
                out[0] = (float)(g_acc[0] / fn);
            }
        }
    }
}

// ---------------------------------------------------------------------------
// Launch
// ---------------------------------------------------------------------------
extern "C" void kernel_launch(void* const* d_in, const int* in_sizes, int n_in,
                              void* d_out, int out_size)
{
    const float* pred_raw = (const float*)d_in[0];   // [N,3]
    const float* u_c      = (const float*)d_in[1];   // [1]
    const float* theta_c  = (const float*)d_in[2];   // [1]
    const float* elem_len = (const float*)d_in[3];   // [E]
    const float* prop_E   = (const float*)d_in[4];   // [E]
    const float* prop_A   = (const float*)d_in[5];   // [E]
    const float* prop_I   = (const float*)d_in[6];   // [E]
    const float* dirs     = (const float*)d_in[7];   // [E,3]
    const float* F_ext    = (const float*)d_in[8];   // [N,3]
    const float* bc_disp  = (const float*)d_in[9];   // [N,1]
    const float* bc_rot   = (const float*)d_in[10];  // [N,1]
    const int*   conn     = (const int*)d_in[11];    // [E,2]

    int N = in_sizes[0] / 3;
    int E = in_sizes[3];

    float* out = (float*)d_out;

    zero_acc_kernel<<<1, 1>>>();

    int nquadN = N >> 2;
    prep_kernel<<<(nquadN + 255) / 256, 256>>>(
        (const float4*)pred_raw, (const float4*)F_ext,
        (const float4*)bc_disp, (const float4*)bc_rot,
        u_c, theta_c, N);

    int nquadE = E >> 2;
    elem_kernel<<<(nquadE + ETB - 1) / ETB, ETB>>>(
        (const float4*)elem_len, (const float4*)prop_E,
        (const float4*)prop_A, (const float4*)prop_I,
        (const float4*)dirs, (const int4*)conn, E);

    int tail = E - (nquadE << 2);
    if (tail > 0) {
        elem_tail_kernel<<<1, 256>>>(elem_len, prop_E, prop_A, prop_I,
                                     dirs, conn, nquadE << 2, E);
    }

    node_kernel<<<(nquadN + 255) / 256, 256>>>(out, N);
}

// round 6
// speedup vs baseline: 1.1312x; 1.0288x over previous
#include <cuda_runtime.h>
#include <cuda_bf16.h>
#include <math.h>

#define MAX_NODES 1000000

// Pre-scaled nodal displacement: {ux*u_c, uy*u_c, th*theta_c, 0}
__device__ float4 g_pred4[MAX_NODES];
// Accumulator: starts at {-Fe_x, -Fe_y, -Fe_z, packed_masks}; elements add
// their forces (w += 0.0f), so after elem pass it holds {R_x, R_y, R_z, masks}.
__device__ float4 g_Fint4[MAX_NODES];
__device__ double g_acc[2] = {0.0, 0.0};  // [0]=sum(R_free^2) [1]=sum(F_free^2)
__device__ unsigned g_done = 0u;          // last-block ticket (reset each launch)

// ---------------------------------------------------------------------------
// Kernel 1: prep — 4 nodes/thread, float4 I/O.
//   g_pred4[i] = scaled displacement
//   g_Fint4[i] = {-F_ext, md + 2*mr}
//   g_acc[1]  += sum(F_free^2)      (g_acc was zeroed by previous launch)
// ---------------------------------------------------------------------------
__global__ void __launch_bounds__(256)
prep_kernel(const float4* __restrict__ pred4,
            const float4* __restrict__ fext4,
            const float4* __restrict__ bcd4,
            const float4* __restrict__ bcr4,
            const float* __restrict__ u_c,
            const float* __restrict__ theta_c,
            int N)
{
    int t = blockIdx.x * blockDim.x + threadIdx.x;   // nodes 4t..4t+3
    int nquad = N >> 2;

    float f2 = 0.f;
    if (t < nquad) {
        float su = __ldg(u_c);
        float st = __ldg(theta_c);

        float4 p0 = __ldcs(&pred4[3 * t + 0]);
        float4 p1 = __ldcs(&pred4[3 * t + 1]);
        float4 p2 = __ldcs(&pred4[3 * t + 2]);
        float4 e0 = __ldcs(&fext4[3 * t + 0]);
        float4 e1 = __ldcs(&fext4[3 * t + 1]);
        float4 e2 = __ldcs(&fext4[3 * t + 2]);
        float4 bd = __ldcs(&bcd4[t]);
        float4 br = __ldcs(&bcr4[t]);

        float px[4] = {p0.x, p0.w, p1.z, p2.y};
        float py[4] = {p0.y, p1.x, p1.w, p2.z};
        float pt[4] = {p0.z, p1.y, p2.x, p2.w};
        float fx[4] = {e0.x, e0.w, e1.z, e2.y};
        float fy[4] = {e0.y, e1.x, e1.w, e2.z};
        float fz[4] = {e0.z, e1.y, e2.x, e2.w};
        float md[4] = {1.f - bd.x, 1.f - bd.y, 1.f - bd.z, 1.f - bd.w};
        float mr[4] = {1.f - br.x, 1.f - br.y, 1.f - br.z, 1.f - br.w};

        #pragma unroll
        for (int k = 0; k < 4; ++k) {
            int node = 4 * t + k;
            g_pred4[node] = make_float4(px[k] * su, py[k] * su, pt[k] * st, 0.f);
            float w = md[k] + 2.f * mr[k];            // {0,1,2,3} exact
            g_Fint4[node] = make_float4(-fx[k], -fy[k], -fz[k], w);
            float G0 = fx[k] * md[k];
            float G1 = fy[k] * md[k];
            float G2 = fz[k] * mr[k];
            f2 += G0 * G0 + G1 * G1 + G2 * G2;
        }
    }

    for (int off = 16; off > 0; off >>= 1)
        f2 += __shfl_down_sync(0xffffffffu, f2, off);
    __shared__ float sf[8];
    int lane = threadIdx.x & 31;
    int wid  = threadIdx.x >> 5;
    if (lane == 0) sf[wid] = f2;
    __syncthreads();
    if (wid == 0) {
        float ff = (lane < 8) ? sf[lane] : 0.f;
        for (int off = 4; off > 0; off >>= 1)
            ff += __shfl_down_sync(0xffffffffu, ff, off);
        if (lane == 0) atomicAdd(&g_acc[1], (double)ff);
    }
}

// ---------------------------------------------------------------------------
// Kernel 2: element pass — 4 adjacent elements/thread, evict-first streamed
// vector loads, front-batched float4 gathers, v4 RED scatter
// ---------------------------------------------------------------------------
#define ETB 256

__device__ __forceinline__ void elem_force(
    float c, float s, float4 dA, float4 dB, float L, float EA, float EI,
    float& fAx, float& fAy, float& f2o, float& f5o)
{
    float thA = -dA.z;
    float thB = -dB.z;

    float u_A =  c * dA.x + s * dA.y;
    float w_A = -s * dA.x + c * dA.y;
    float u_B =  c * dB.x + s * dB.y;
    float w_B = -s * dB.x + c * dB.y;

    float inv_l = 1.0f / L;
    float ea_l  = EA * inv_l;
    float ei_l  = EI * inv_l;
    float ei_l2 = ei_l * inv_l;
    float ei_l3 = ei_l2 * inv_l;

    float dw = w_A - w_B;
    float f0 = ea_l * (u_A - u_B);
    float f1 = 12.0f * ei_l3 * dw + 6.0f * ei_l2 * (thA + thB);
    f2o = 6.0f * ei_l2 * dw + 4.0f * ei_l * thA + 2.0f * ei_l * thB;
    f5o = 6.0f * ei_l2 * dw + 2.0f * ei_l * thA + 4.0f * ei_l * thB;

    fAx = c * f0 - s * f1;
    fAy = s * f0 + c * f1;
}

__device__ __forceinline__ void red_v4(float4* p, float a, float b, float cc)
{
    asm volatile("red.global.add.v4.f32 [%0], {%1, %2, %3, %4};"
                 :: "l"(p), "f"(a), "f"(b), "f"(cc), "f"(0.f)
                 : "memory");
}

__global__ void __launch_bounds__(ETB)
elem_kernel(const float4* __restrict__ len4,
            const float4* __restrict__ pE4,
            const float4* __restrict__ pA4,
            const float4* __restrict__ pI4,
            const float4* __restrict__ dir4,
            const int4*  __restrict__ conn4,
            int E)
{
    int t = blockIdx.x * ETB + threadIdx.x;     // elements 4t..4t+3
    int nquad = E >> 2;
    if (t >= nquad) return;

    // ---- streamed vector loads, evict-first (read-once data) ----
    int4   cnA = __ldcs(&conn4[2 * t + 0]);
    int4   cnB = __ldcs(&conn4[2 * t + 1]);
    float4 Lq  = __ldcs(&len4[t]);
    float4 Eq  = __ldcs(&pE4[t]);
    float4 Aq  = __ldcs(&pA4[t]);
    float4 Iq  = __ldcs(&pI4[t]);
    float4 q0  = __ldcs(&dir4[3 * t + 0]);
    float4 q1  = __ldcs(&dir4[3 * t + 1]);
    float4 q2  = __ldcs(&dir4[3 * t + 2]);

    // ---- front-batched gathers (8 outstanding LDG.128, L2-resident) ----
    float4 dA0 = __ldg(&g_pred4[cnA.x]);
    float4 dB0 = __ldg(&g_pred4[cnA.y]);
    float4 dA1 = __ldg(&g_pred4[cnA.z]);
    float4 dB1 = __ldg(&g_pred4[cnA.w]);
    float4 dA2 = __ldg(&g_pred4[cnB.x]);
    float4 dB2 = __ldg(&g_pred4[cnB.y]);
    float4 dA3 = __ldg(&g_pred4[cnB.z]);
    float4 dB3 = __ldg(&g_pred4[cnB.w]);

    float c0 = q0.x, s0 = q0.z;
    float c1 = q0.w, s1 = q1.y;
    float c2 = q1.z, s2 = q2.x;
    float c3 = q2.y, s3 = q2.w;

    float fAx, fAy, f2, f5;

    elem_force(c0, s0, dA0, dB0, Lq.x, Eq.x * Aq.x, Eq.x * Iq.x, fAx, fAy, f2, f5);
    red_v4(&g_Fint4[cnA.x],  fAx,  fAy, -f2);
    red_v4(&g_Fint4[cnA.y], -fAx, -fAy, -f5);

    elem_force(c1, s1, dA1, dB1, Lq.y, Eq.y * Aq.y, Eq.y * Iq.y, fAx, fAy, f2, f5);
    red_v4(&g_Fint4[cnA.z],  fAx,  fAy, -f2);
    red_v4(&g_Fint4[cnA.w], -fAx, -fAy, -f5);

    elem_force(c2, s2, dA2, dB2, Lq.z, Eq.z * Aq.z, Eq.z * Iq.z, fAx, fAy, f2, f5);
    red_v4(&g_Fint4[cnB.x],  fAx,  fAy, -f2);
    red_v4(&g_Fint4[cnB.y], -fAx, -fAy, -f5);

    elem_force(c3, s3, dA3, dB3, Lq.w, Eq.w * Aq.w, Eq.w * Iq.w, fAx, fAy, f2, f5);
    red_v4(&g_Fint4[cnB.z],  fAx,  fAy, -f2);
    red_v4(&g_Fint4[cnB.w], -fAx, -fAy, -f5);
}

// tail for E % 4 != 0 (not launched for E = 2M)
__global__ void elem_tail_kernel(const float* __restrict__ elem_len,
                                 const float* __restrict__ prop_E,
                                 const float* __restrict__ prop_A,
                                 const float* __restrict__ prop_I,
                                 const float* __restrict__ dirs,
                                 const int*  __restrict__ conn,
                                 int start, int E)
{
    int e = start + blockIdx.x * blockDim.x + threadIdx.x;
    if (e >= E) return;
    int nA = conn[2 * e + 0];
    int nB = conn[2 * e + 1];
    float c = dirs[3 * e + 0];
    float s = dirs[3 * e + 2];
    float pe = prop_E[e];
    float4 dA = __ldg(&g_pred4[nA]);
    float4 dB = __ldg(&g_pred4[nB]);
    float fAx, fAy, f2, f5;
    elem_force(c, s, dA, dB, elem_len[e], pe * prop_A[e], pe * prop_I[e],
               fAx, fAy, f2, f5);
    red_v4(&g_Fint4[nA],  fAx,  fAy, -f2);
    red_v4(&g_Fint4[nB], -fAx, -fAy, -f5);
}

// ---------------------------------------------------------------------------
// Kernel 3: node pass — 8 nodes/thread (MLP 8), fused final divide + state
// reset for the next launch (graph replay).
// ---------------------------------------------------------------------------
__global__ void __launch_bounds__(256)
node_kernel(float* __restrict__ out, int N)
{
    int t = blockIdx.x * blockDim.x + threadIdx.x;   // nodes 8t..8t+7
    int noct = N >> 3;

    float r2 = 0.f;
    if (t < noct) {
        float4 v[8];
        #pragma unroll
        for (int k = 0; k < 8; ++k) v[k] = g_Fint4[8 * t + k];

        #pragma unroll
        for (int k = 0; k < 8; ++k) {
            int iw = (int)v[k].w;
            float md = (float)(iw & 1);
            float mr = (float)(iw >> 1);
            float R0 = v[k].x * md;
            float R1 = v[k].y * md;
            float R2 = v[k].z * mr;
            r2 += R0 * R0 + R1 * R1 + R2 * R2;
        }
    }
    // tail nodes (N % 8) handled by first threads of block 0
    int tailStart = noct << 3;
    if (blockIdx.x == 0 && threadIdx.x < (N - tailStart)) {
        float4 Fi = g_Fint4[tailStart + threadIdx.x];
        int iw = (int)Fi.w;
        float md = (float)(iw & 1);
        float mr = (float)(iw >> 1);
        float R0 = Fi.x * md;
        float R1 = Fi.y * md;
        float R2 = Fi.z * mr;
        r2 += R0 * R0 + R1 * R1 + R2 * R2;
    }

    for (int off = 16; off > 0; off >>= 1)
        r2 += __shfl_down_sync(0xffffffffu, r2, off);

    __shared__ float sr[8];
    int lane = threadIdx.x & 31;
    int wid  = threadIdx.x >> 5;
    if (lane == 0) sr[wid] = r2;
    __syncthreads();

    if (wid == 0) {
        float rr = (lane < 8) ? sr[lane] : 0.f;
        for (int off = 4; off > 0; off >>= 1)
            rr += __shfl_down_sync(0xffffffffu, rr, off);
        if (lane == 0) {
            atomicAdd(&g_acc[0], (double)rr);
            __threadfence();
            unsigned ticket = atomicAdd(&g_done, 1u);
            if (ticket == gridDim.x - 1) {
                double fn = g_acc[1];
                if (fn < 1e-30) fn = 1e-30;
                out[0] = (float)(g_acc[0] / fn);
                // reset state for next launch (deterministic across replays)
                g_acc[0] = 0.0;
                g_acc[1] = 0.0;
                g_done = 0u;
            }
        }
    }
}

// ---------------------------------------------------------------------------
// Launch
// ---------------------------------------------------------------------------
extern "C" void kernel_launch(void* const* d_in, const int* in_sizes, int n_in,
                              void* d_out, int out_size)
{
    const float* pred_raw = (const float*)d_in[0];   // [N,3]
    const float* u_c      = (const float*)d_in[1];   // [1]
    const float* theta_c  = (const float*)d_in[2];   // [1]
    const float* elem_len = (const float*)d_in[3];   // [E]
    const float* prop_E   = (const float*)d_in[4];   // [E]
    const float* prop_A   = (const float*)d_in[5];   // [E]
    const float* prop_I   = (const float*)d_in[6];   // [E]
    const float* dirs     = (const float*)d_in[7];   // [E,3]
    const float* F_ext    = (const float*)d_in[8];   // [N,3]
    const float* bc_disp  = (const float*)d_in[9];   // [N,1]
    const float* bc_rot   = (const float*)d_in[10];  // [N,1]
    const int*   conn     = (const int*)d_in[11];    // [E,2]

    int N = in_sizes[0] / 3;
    int E = in_sizes[3];

    float* out = (float*)d_out;

    int nquadN = N >> 2;
    prep_kernel<<<(nquadN + 255) / 256, 256>>>(
        (const float4*)pred_raw, (const float4*)F_ext,
        (const float4*)bc_disp, (const float4*)bc_rot,
        u_c, theta_c, N);

    int nquadE = E >> 2;
    elem_kernel<<<(nquadE + ETB - 1) / ETB, ETB>>>(
        (const float4*)elem_len, (const float4*)prop_E,
        (const float4*)prop_A, (const float4*)prop_I,
        (const float4*)dirs, (const int4*)conn, E);

    int tail = E - (nquadE << 2);
    if (tail > 0) {
        elem_tail_kernel<<<1, 256>>>(elem_len, prop_E, prop_A, prop_I,
                                     dirs, conn, nquadE << 2, E);
    }

    int noct = N >> 3;
    node_kernel<<<(noct + 255) / 256, 256>>>(out, N);
}

// round 7
// speedup vs baseline: 1.1747x; 1.0385x over previous
#include <cuda_runtime.h>
#include <cuda_bf16.h>
#include <math.h>

#define MAX_NODES 1000000

// Pre-scaled nodal displacement: {ux*u_c, uy*u_c, th*theta_c, 0}
__device__ float4 g_pred4[MAX_NODES];
// Accumulator: starts at {-Fe_x, -Fe_y, -Fe_z, packed_masks}; elements add
// forces (w += 0.0f) so after elem pass it holds {R_x, R_y, R_z, masks}.
__device__ float4 g_Fint4[MAX_NODES];
__device__ double g_acc[2] = {0.0, 0.0};  // [0]=sum(R_free^2) [1]=sum(F_free^2)
__device__ unsigned g_done = 0u;          // last-block ticket (reset each launch)

// ---------------------------------------------------------------------------
// Kernel 1: prep — smem-staged, fully coalesced. 256 nodes/block.
// ---------------------------------------------------------------------------
__global__ void __launch_bounds__(256)
prep_kernel(const float4* __restrict__ pred4,   // 3N/4 float4
            const float4* __restrict__ fext4,   // 3N/4 float4
            const float4* __restrict__ bcd4,    // N/4 float4
            const float4* __restrict__ bcr4,    // N/4 float4
            const float* __restrict__ u_c,
            const float* __restrict__ theta_c,
            int N)
{
    __shared__ float spred[768];
    __shared__ float sfext[768];
    __shared__ float sbcd[256];
    __shared__ float sbcr[256];

    int tid = threadIdx.x;
    int b   = blockIdx.x;

    int npred4 = (3 * N) >> 2;   // total float4 in pred/fext
    int nbc4   = N >> 2;

    // coalesced staging loads
    {
        int g = b * 192 + tid;               // 192 float4 per block
        if (tid < 192) {
            float4 p = (g < npred4) ? __ldcs(&pred4[g]) : make_float4(0,0,0,0);
            float4 f = (g < npred4) ? __ldcs(&fext4[g]) : make_float4(0,0,0,0);
            ((float4*)spred)[tid] = p;
            ((float4*)sfext)[tid] = f;
        }
        int gb = b * 64 + (tid & 63);
        if (tid < 64) {
            float4 d = (gb < nbc4) ? __ldcs(&bcd4[gb]) : make_float4(0,0,0,0);
            ((float4*)sbcd)[tid] = d;
        } else if (tid < 128) {
            float4 r = (gb < nbc4) ? __ldcs(&bcr4[gb]) : make_float4(0,0,0,0);
            ((float4*)sbcr)[tid - 64] = r;
        }
    }
    __syncthreads();

    float f2 = 0.f;
    int node = b * 256 + tid;
    if (node < N) {
        float su = __ldg(u_c);
        float st = __ldg(theta_c);

        float px = spred[3 * tid + 0];
        float py = spred[3 * tid + 1];
        float pt = spred[3 * tid + 2];
        float fx = sfext[3 * tid + 0];
        float fy = sfext[3 * tid + 1];
        float fz = sfext[3 * tid + 2];
        float md = 1.f - sbcd[tid];
        float mr = 1.f - sbcr[tid];

        g_pred4[node] = make_float4(px * su, py * su, pt * st, 0.f);  // coalesced
        float w = md + 2.f * mr;                                      // {0,1,2,3}
        g_Fint4[node] = make_float4(-fx, -fy, -fz, w);                // coalesced

        float G0 = fx * md;
        float G1 = fy * md;
        float G2 = fz * mr;
        f2 = G0 * G0 + G1 * G1 + G2 * G2;
    }

    for (int off = 16; off > 0; off >>= 1)
        f2 += __shfl_down_sync(0xffffffffu, f2, off);
    __shared__ float sf[8];
    int lane = tid & 31;
    int wid  = tid >> 5;
    if (lane == 0) sf[wid] = f2;
    __syncthreads();
    if (wid == 0) {
        float ff = (lane < 8) ? sf[lane] : 0.f;
        for (int off = 4; off > 0; off >>= 1)
            ff += __shfl_down_sync(0xffffffffu, ff, off);
        if (lane == 0) atomicAdd(&g_acc[1], (double)ff);
    }
}

// ---------------------------------------------------------------------------
// Kernel 2: element pass — 4 elem/thread; dirs+conn smem-staged (coalesced),
// props/len direct coalesced float4, batched gathers, v4 RED scatter.
// ---------------------------------------------------------------------------
#define ETB 256
#define EPB (4 * ETB)    // 1024 elements per block

__device__ __forceinline__ void elem_force(
    float c, float s, float4 dA, float4 dB, float L, float EA, float EI,
    float& fAx, float& fAy, float& f2o, float& f5o)
{
    float thA = -dA.z;
    float thB = -dB.z;

    float u_A =  c * dA.x + s * dA.y;
    float w_A = -s * dA.x + c * dA.y;
    float u_B =  c * dB.x + s * dB.y;
    float w_B = -s * dB.x + c * dB.y;

    float inv_l = 1.0f / L;
    float ea_l  = EA * inv_l;
    float ei_l  = EI * inv_l;
    float ei_l2 = ei_l * inv_l;
    float ei_l3 = ei_l2 * inv_l;

    float dw = w_A - w_B;
    float f0 = ea_l * (u_A - u_B);
    float f1 = 12.0f * ei_l3 * dw + 6.0f * ei_l2 * (thA + thB);
    f2o = 6.0f * ei_l2 * dw + 4.0f * ei_l * thA + 2.0f * ei_l * thB;
    f5o = 6.0f * ei_l2 * dw + 2.0f * ei_l * thA + 4.0f * ei_l * thB;

    fAx = c * f0 - s * f1;
    fAy = s * f0 + c * f1;
}

__device__ __forceinline__ void red_v4(float4* p, float a, float b, float cc)
{
    asm volatile("red.global.add.v4.f32 [%0], {%1, %2, %3, %4};"
                 :: "l"(p), "f"(a), "f"(b), "f"(cc), "f"(0.f)
                 : "memory");
}

__global__ void __launch_bounds__(ETB)
elem_kernel(const float4* __restrict__ len4,
            const float4* __restrict__ pE4,
            const float4* __restrict__ pA4,
            const float4* __restrict__ pI4,
            const float4* __restrict__ dir4,    // 3E/4 float4
            const int4*  __restrict__ conn4,    // E/2 int4
            int E)
{
    __shared__ float sdir[3 * EPB];             // 12 KB
    __shared__ int   sconn[2 * EPB];            // 8 KB

    int tid = threadIdx.x;
    int b   = blockIdx.x;

    // coalesced staging: dirs (768 float4/block), conn (512 int4/block)
    int ndir4  = (3 * E) >> 2;
    int nconn4 = E >> 1;
    #pragma unroll
    for (int k = 0; k < 3; ++k) {
        int g = b * 768 + k * ETB + tid;
        ((float4*)sdir)[k * ETB + tid] =
            (g < ndir4) ? __ldcs(&dir4[g]) : make_float4(0,0,0,0);
    }
    #pragma unroll
    for (int k = 0; k < 2; ++k) {
        int g = b * 512 + k * ETB + tid;
        ((int4*)sconn)[k * ETB + tid] =
            (g < nconn4) ? __ldcs(&conn4[g]) : make_int4(0,0,0,0);
    }
    __syncthreads();

    int qt = b * ETB + tid;          // quad index: elements 4qt..4qt+3
    int nquad = E >> 2;
    if (qt >= nquad) return;

    // coalesced streamed vector loads
    float4 Lq = __ldcs(&len4[qt]);
    float4 Eq = __ldcs(&pE4[qt]);
    float4 Aq = __ldcs(&pA4[qt]);
    float4 Iq = __ldcs(&pI4[qt]);

    // conn from smem
    int nA0 = sconn[8 * tid + 0], nB0 = sconn[8 * tid + 1];
    int nA1 = sconn[8 * tid + 2], nB1 = sconn[8 * tid + 3];
    int nA2 = sconn[8 * tid + 4], nB2 = sconn[8 * tid + 5];
    int nA3 = sconn[8 * tid + 6], nB3 = sconn[8 * tid + 7];

    // front-batched gathers (8 outstanding LDG.128)
    float4 dA0 = __ldg(&g_pred4[nA0]);
    float4 dB0 = __ldg(&g_pred4[nB0]);
    float4 dA1 = __ldg(&g_pred4[nA1]);
    float4 dB1 = __ldg(&g_pred4[nB1]);
    float4 dA2 = __ldg(&g_pred4[nA2]);
    float4 dB2 = __ldg(&g_pred4[nB2]);
    float4 dA3 = __ldg(&g_pred4[nA3]);
    float4 dB3 = __ldg(&g_pred4[nB3]);

    // dirs from smem: c_k = [12t+3k], s_k = [12t+3k+2]
    float c0 = sdir[12 * tid + 0],  s0 = sdir[12 * tid + 2];
    float c1 = sdir[12 * tid + 3],  s1 = sdir[12 * tid + 5];
    float c2 = sdir[12 * tid + 6],  s2 = sdir[12 * tid + 8];
    float c3 = sdir[12 * tid + 9],  s3 = sdir[12 * tid + 11];

    float fAx, fAy, f2, f5;

    elem_force(c0, s0, dA0, dB0, Lq.x, Eq.x * Aq.x, Eq.x * Iq.x, fAx, fAy, f2, f5);
    red_v4(&g_Fint4[nA0],  fAx,  fAy, -f2);
    red_v4(&g_Fint4[nB0], -fAx, -fAy, -f5);

    elem_force(c1, s1, dA1, dB1, Lq.y, Eq.y * Aq.y, Eq.y * Iq.y, fAx, fAy, f2, f5);
    red_v4(&g_Fint4[nA1],  fAx,  fAy, -f2);
    red_v4(&g_Fint4[nB1], -fAx, -fAy, -f5);

    elem_force(c2, s2, dA2, dB2, Lq.z, Eq.z * Aq.z, Eq.z * Iq.z, fAx, fAy, f2, f5);
    red_v4(&g_Fint4[nA2],  fAx,  fAy, -f2);
    red_v4(&g_Fint4[nB2], -fAx, -fAy, -f5);

    elem_force(c3, s3, dA3, dB3, Lq.w, Eq.w * Aq.w, Eq.w * Iq.w, fAx, fAy, f2, f5);
    red_v4(&g_Fint4[nA3],  fAx,  fAy, -f2);
    red_v4(&g_Fint4[nB3], -fAx, -fAy, -f5);
}

// tail for E % 4 != 0 (not launched for E = 2M)
__global__ void elem_tail_kernel(const float* __restrict__ elem_len,
                                 const float* __restrict__ prop_E,
                                 const float* __restrict__ prop_A,
                                 const float* __restrict__ prop_I,
                                 const float* __restrict__ dirs,
                                 const int*  __restrict__ conn,
                                 int start, int E)
{
    int e = start + blockIdx.x * blockDim.x + threadIdx.x;
    if (e >= E) return;
    int nA = conn[2 * e + 0];
    int nB = conn[2 * e + 1];
    float c = dirs[3 * e + 0];
    float s = dirs[3 * e + 2];
    float pe = prop_E[e];
    float4 dA = __ldg(&g_pred4[nA]);
    float4 dB = __ldg(&g_pred4[nB]);
    float fAx, fAy, f2, f5;
    elem_force(c, s, dA, dB, elem_len[e], pe * prop_A[e], pe * prop_I[e],
               fAx, fAy, f2, f5);
    red_v4(&g_Fint4[nA],  fAx,  fAy, -f2);
    red_v4(&g_Fint4[nB], -fAx, -fAy, -f5);
}

// ---------------------------------------------------------------------------
// Kernel 3: node pass — COALESCED 8-deep loads (block covers 2048 nodes),
// fused final divide + state reset.
// ---------------------------------------------------------------------------
__global__ void __launch_bounds__(256)
node_kernel(float* __restrict__ out, int N)
{
    int tid  = threadIdx.x;
    int base = blockIdx.x * 2048;

    float4 v[8];
    #pragma unroll
    for (int k = 0; k < 8; ++k) {
        int idx = base + k * 256 + tid;      // lane-contiguous: coalesced
        v[k] = (idx < N) ? g_Fint4[idx] : make_float4(0.f, 0.f, 0.f, 0.f);
    }

    float r2 = 0.f;
    #pragma unroll
    for (int k = 0; k < 8; ++k) {
        int iw = (int)v[k].w;
        float md = (float)(iw & 1);
        float mr = (float)(iw >> 1);
        float R0 = v[k].x * md;
        float R1 = v[k].y * md;
        float R2 = v[k].z * mr;
        r2 += R0 * R0 + R1 * R1 + R2 * R2;
    }

    for (int off = 16; off > 0; off >>= 1)
        r2 += __shfl_down_sync(0xffffffffu, r2, off);

    __shared__ float sr[8];
    int lane = tid & 31;
    int wid  = tid >> 5;
    if (lane == 0) sr[wid] = r2;
    __syncthreads();

    if (wid == 0) {
        float rr = (lane < 8) ? sr[lane] : 0.f;
        for (int off = 4; off > 0; off >>= 1)
            rr += __shfl_down_sync(0xffffffffu, rr, off);
        if (lane == 0) {
            atomicAdd(&g_acc[0], (double)rr);
            __threadfence();
            unsigned ticket = atomicAdd(&g_done, 1u);
            if (ticket == gridDim.x - 1) {
                double fn = g_acc[1];
                if (fn < 1e-30) fn = 1e-30;
                out[0] = (float)(g_acc[0] / fn);
                g_acc[0] = 0.0;
                g_acc[1] = 0.0;
                g_done = 0u;
            }
        }
    }
}

// ---------------------------------------------------------------------------
// Launch
// ---------------------------------------------------------------------------
extern "C" void kernel_launch(void* const* d_in, const int* in_sizes, int n_in,
                              void* d_out, int out_size)
{
    const float* pred_raw = (const float*)d_in[0];   // [N,3]
    const float* u_c      = (const float*)d_in[1];   // [1]
    const float* theta_c  = (const float*)d_in[2];   // [1]
    const float* elem_len = (const float*)d_in[3];   // [E]
    const float* prop_E   = (const float*)d_in[4];   // [E]
    const float* prop_A   = (const float*)d_in[5];   // [E]
    const float* prop_I   = (const float*)d_in[6];   // [E]
    const float* dirs     = (const float*)d_in[7];   // [E,3]
    const float* F_ext    = (const float*)d_in[8];   // [N,3]
    const float* bc_disp  = (const float*)d_in[9];   // [N,1]
    const float* bc_rot   = (const float*)d_in[10];  // [N,1]
    const int*   conn     = (const int*)d_in[11];    // [E,2]

    int N = in_sizes[0] / 3;
    int E = in_sizes[3];

    float* out = (float*)d_out;

    prep_kernel<<<(N + 255) / 256, 256>>>(
        (const float4*)pred_raw, (const float4*)F_ext,
        (const float4*)bc_disp, (const float4*)bc_rot,
        u_c, theta_c, N);

    elem_kernel<<<(E + EPB - 1) / EPB, ETB>>>(
        (const float4*)elem_len, (const float4*)prop_E,
        (const float4*)prop_A, (const float4*)prop_I,
        (const float4*)dirs, (const int4*)conn, E);

    int tail = E & 3;
    if (tail > 0) {
        elem_tail_kernel<<<1, 256>>>(elem_len, prop_E, prop_A, prop_I,
                                     dirs, conn, E & ~3, E);
    }

    node_kernel<<<(N + 2047) / 2048, 256>>>(out, N);
}

// round 8
// speedup vs baseline: 1.2096x; 1.0297x over previous
#include <cuda_runtime.h>
#include <cuda_bf16.h>
#include <math.h>

#define MAX_NODES 1000000

// Pre-scaled nodal displacement: {ux*u_c, uy*u_c, th*theta_c, 0}
__device__ float4 g_pred4[MAX_NODES];
// Accumulator: starts at {-Fe_x, -Fe_y, -Fe_z, packed_masks}; elements add
// forces (w += 0.0f) so after elem pass it holds {R_x, R_y, R_z, masks}.
__device__ float4 g_Fint4[MAX_NODES];
__device__ double g_acc[2] = {0.0, 0.0};  // [0]=sum(R_free^2) [1]=sum(F_free^2)
__device__ unsigned g_done = 0u;          // last-block ticket (reset each launch)

// ---------------------------------------------------------------------------
// Kernel 1: prep — 512 nodes/block, 2 nodes/thread, smem staging for the
// stride-3 arrays, direct coalesced loads for bc. High MLP.
// ---------------------------------------------------------------------------
#define PTB 256          // threads
#define NPB 512          // nodes per block

__global__ void __launch_bounds__(PTB)
prep_kernel(const float4* __restrict__ pred4,   // 3N/4 float4
            const float4* __restrict__ fext4,   // 3N/4 float4
            const float* __restrict__ bc_disp,  // N
            const float* __restrict__ bc_rot,   // N
            const float* __restrict__ u_c,
            const float* __restrict__ theta_c,
            int N)
{
    __shared__ float spred[3 * NPB];   // 1536 floats = 384 float4
    __shared__ float sfext[3 * NPB];

    int tid  = threadIdx.x;
    int b    = blockIdx.x;
    int base = b * NPB;

    int npred4 = (3 * N) >> 2;

    // front-batch everything: staged vector loads + direct bc loads
    int n0 = base + tid;
    int n1 = base + PTB + tid;
    bool v0 = (n0 < N);
    bool v1 = (n1 < N);

    float bd0 = v0 ? __ldcs(&bc_disp[n0]) : 0.f;
    float br0 = v0 ? __ldcs(&bc_rot[n0])  : 0.f;
    float bd1 = v1 ? __ldcs(&bc_disp[n1]) : 0.f;
    float br1 = v1 ? __ldcs(&bc_rot[n1])  : 0.f;

    {
        int g0 = b * 384 + tid;                     // round 0: 256 float4
        float4 p0 = (g0 < npred4) ? __ldcs(&pred4[g0]) : make_float4(0,0,0,0);
        float4 f0 = (g0 < npred4) ? __ldcs(&fext4[g0]) : make_float4(0,0,0,0);
        int g1 = b * 384 + 256 + tid;               // round 1: 128 float4
        float4 p1 = make_float4(0,0,0,0), f1 = p1;
        if (tid < 128) {
            if (g1 < npred4) { p1 = __ldcs(&pred4[g1]); f1 = __ldcs(&fext4[g1]); }
        }
        ((float4*)spred)[tid] = p0;
        ((float4*)sfext)[tid] = f0;
        if (tid < 128) {
            ((float4*)spred)[256 + tid] = p1;
            ((float4*)sfext)[256 + tid] = f1;
        }
    }
    __syncthreads();

    float su = __ldg(u_c);
    float st = __ldg(theta_c);

    float f2 = 0.f;

    // node 0: smem index = tid; node 1: smem index = tid + PTB
    #pragma unroll
    for (int k = 0; k < 2; ++k) {
        int node = (k == 0) ? n0 : n1;
        if (node >= N) continue;
        int si = (k == 0) ? tid : (tid + PTB);

        float px = spred[3 * si + 0];
        float py = spred[3 * si + 1];
        float pt = spred[3 * si + 2];
        float fx = sfext[3 * si + 0];
        float fy = sfext[3 * si + 1];
        float fz = sfext[3 * si + 2];
        float md = 1.f - ((k == 0) ? bd0 : bd1);
        float mr = 1.f - ((k == 0) ? br0 : br1);

        g_pred4[node] = make_float4(px * su, py * su, pt * st, 0.f);
        float w = md + 2.f * mr;                  // {0,1,2,3} exact
        g_Fint4[node] = make_float4(-fx, -fy, -fz, w);

        float G0 = fx * md;
        float G1 = fy * md;
        float G2 = fz * mr;
        f2 += G0 * G0 + G1 * G1 + G2 * G2;
    }

    for (int off = 16; off > 0; off >>= 1)
        f2 += __shfl_down_sync(0xffffffffu, f2, off);
    __shared__ float sf[8];
    int lane = tid & 31;
    int wid  = tid >> 5;
    if (lane == 0) sf[wid] = f2;
    __syncthreads();
    if (wid == 0) {
        float ff = (lane < 8) ? sf[lane] : 0.f;
        for (int off = 4; off > 0; off >>= 1)
            ff += __shfl_down_sync(0xffffffffu, ff, off);
        if (lane == 0) atomicAdd(&g_acc[1], (double)ff);
    }
}

// ---------------------------------------------------------------------------
// Kernel 2: element pass — 4 elem/thread; dirs+conn smem-staged (coalesced),
// props/len direct coalesced float4, batched gathers, v4 RED scatter.
// ---------------------------------------------------------------------------
#define ETB 256
#define EPB (4 * ETB)    // 1024 elements per block

__device__ __forceinline__ void elem_force(
    float c, float s, float4 dA, float4 dB, float L, float EA, float EI,
    float& fAx, float& fAy, float& f2o, float& f5o)
{
    float thA = -dA.z;
    float thB = -dB.z;

    float u_A =  c * dA.x + s * dA.y;
    float w_A = -s * dA.x + c * dA.y;
    float u_B =  c * dB.x + s * dB.y;
    float w_B = -s * dB.x + c * dB.y;

    float inv_l = 1.0f / L;
    float ea_l  = EA * inv_l;
    float ei_l  = EI * inv_l;
    float ei_l2 = ei_l * inv_l;
    float ei_l3 = ei_l2 * inv_l;

    float dw = w_A - w_B;
    float f0 = ea_l * (u_A - u_B);
    float f1 = 12.0f * ei_l3 * dw + 6.0f * ei_l2 * (thA + thB);
    f2o = 6.0f * ei_l2 * dw + 4.0f * ei_l * thA + 2.0f * ei_l * thB;
    f5o = 6.0f * ei_l2 * dw + 2.0f * ei_l * thA + 4.0f * ei_l * thB;

    fAx = c * f0 - s * f1;
    fAy = s * f0 + c * f1;
}

__device__ __forceinline__ void red_v4(float4* p, float a, float b, float cc)
{
    asm volatile("red.global.add.v4.f32 [%0], {%1, %2, %3, %4};"
                 :: "l"(p), "f"(a), "f"(b), "f"(cc), "f"(0.f)
                 : "memory");
}

__global__ void __launch_bounds__(ETB)
elem_kernel(const float4* __restrict__ len4,
            const float4* __restrict__ pE4,
            const float4* __restrict__ pA4,
            const float4* __restrict__ pI4,
            const float4* __restrict__ dir4,    // 3E/4 float4
            const int4*  __restrict__ conn4,    // E/2 int4
            int E)
{
    __shared__ float sdir[3 * EPB];             // 12 KB
    __shared__ int   sconn[2 * EPB];            // 8 KB

    int tid = threadIdx.x;
    int b   = blockIdx.x;

    int ndir4  = (3 * E) >> 2;
    int nconn4 = E >> 1;
    #pragma unroll
    for (int k = 0; k < 3; ++k) {
        int g = b * 768 + k * ETB + tid;
        ((float4*)sdir)[k * ETB + tid] =
            (g < ndir4) ? __ldcs(&dir4[g]) : make_float4(0,0,0,0);
    }
    #pragma unroll
    for (int k = 0; k < 2; ++k) {
        int g = b * 512 + k * ETB + tid;
        ((int4*)sconn)[k * ETB + tid] =
            (g < nconn4) ? __ldcs(&conn4[g]) : make_int4(0,0,0,0);
    }
    __syncthreads();

    int qt = b * ETB + tid;          // quad index: elements 4qt..4qt+3
    int nquad = E >> 2;
    if (qt >= nquad) return;

    float4 Lq = __ldcs(&len4[qt]);
    float4 Eq = __ldcs(&pE4[qt]);
    float4 Aq = __ldcs(&pA4[qt]);
    float4 Iq = __ldcs(&pI4[qt]);

    int nA0 = sconn[8 * tid + 0], nB0 = sconn[8 * tid + 1];
    int nA1 = sconn[8 * tid + 2], nB1 = sconn[8 * tid + 3];
    int nA2 = sconn[8 * tid + 4], nB2 = sconn[8 * tid + 5];
    int nA3 = sconn[8 * tid + 6], nB3 = sconn[8 * tid + 7];

    float4 dA0 = __ldg(&g_pred4[nA0]);
    float4 dB0 = __ldg(&g_pred4[nB0]);
    float4 dA1 = __ldg(&g_pred4[nA1]);
    float4 dB1 = __ldg(&g_pred4[nB1]);
    float4 dA2 = __ldg(&g_pred4[nA2]);
    float4 dB2 = __ldg(&g_pred4[nB2]);
    float4 dA3 = __ldg(&g_pred4[nA3]);
    float4 dB3 = __ldg(&g_pred4[nB3]);

    float c0 = sdir[12 * tid + 0],  s0 = sdir[12 * tid + 2];
    float c1 = sdir[12 * tid + 3],  s1 = sdir[12 * tid + 5];
    float c2 = sdir[12 * tid + 6],  s2 = sdir[12 * tid + 8];
    float c3 = sdir[12 * tid + 9],  s3 = sdir[12 * tid + 11];

    float fAx, fAy, f2, f5;

    elem_force(c0, s0, dA0, dB0, Lq.x, Eq.x * Aq.x, Eq.x * Iq.x, fAx, fAy, f2, f5);
    red_v4(&g_Fint4[nA0],  fAx,  fAy, -f2);
    red_v4(&g_Fint4[nB0], -fAx, -fAy, -f5);

    elem_force(c1, s1, dA1, dB1, Lq.y, Eq.y * Aq.y, Eq.y * Iq.y, fAx, fAy, f2, f5);
    red_v4(&g_Fint4[nA1],  fAx,  fAy, -f2);
    red_v4(&g_Fint4[nB1], -fAx, -fAy, -f5);

    elem_force(c2, s2, dA2, dB2, Lq.z, Eq.z * Aq.z, Eq.z * Iq.z, fAx, fAy, f2, f5);
    red_v4(&g_Fint4[nA2],  fAx,  fAy, -f2);
    red_v4(&g_Fint4[nB2], -fAx, -fAy, -f5);

    elem_force(c3, s3, dA3, dB3, Lq.w, Eq.w * Aq.w, Eq.w * Iq.w, fAx, fAy, f2, f5);
    red_v4(&g_Fint4[nA3],  fAx,  fAy, -f2);
    red_v4(&g_Fint4[nB3], -fAx, -fAy, -f5);
}

// tail for E % 4 != 0 (not launched for E = 2M)
__global__ void elem_tail_kernel(const float* __restrict__ elem_len,
                                 const float* __restrict__ prop_E,
                                 const float* __restrict__ prop_A,
                                 const float* __restrict__ prop_I,
                                 const float* __restrict__ dirs,
                                 const int*  __restrict__ conn,
                                 int start, int E)
{
    int e = start + blockIdx.x * blockDim.x + threadIdx.x;
    if (e >= E) return;
    int nA = conn[2 * e + 0];
    int nB = conn[2 * e + 1];
    float c = dirs[3 * e + 0];
    float s = dirs[3 * e + 2];
    float pe = prop_E[e];
    float4 dA = __ldg(&g_pred4[nA]);
    float4 dB = __ldg(&g_pred4[nB]);
    float fAx, fAy, f2, f5;
    elem_force(c, s, dA, dB, elem_len[e], pe * prop_A[e], pe * prop_I[e],
               fAx, fAy, f2, f5);
    red_v4(&g_Fint4[nA],  fAx,  fAy, -f2);
    red_v4(&g_Fint4[nB], -fAx, -fAy, -f5);
}

// ---------------------------------------------------------------------------
// Kernel 3: node pass — coalesced 8-deep loads (block covers 2048 nodes),
// fused final divide + state reset.
// ---------------------------------------------------------------------------
__global__ void __launch_bounds__(256)
node_kernel(float* __restrict__ out, int N)
{
    int tid  = threadIdx.x;
    int base = blockIdx.x * 2048;

    float4 v[8];
    #pragma unroll
    for (int k = 0; k < 8; ++k) {
        int idx = base + k * 256 + tid;      // lane-contiguous: coalesced
        v[k] = (idx < N) ? g_Fint4[idx] : make_float4(0.f, 0.f, 0.f, 0.f);
    }

    float r2 = 0.f;
    #pragma unroll
    for (int k = 0; k < 8; ++k) {
        int iw = (int)v[k].w;
        float md = (float)(iw & 1);
        float mr = (float)(iw >> 1);
        float R0 = v[k].x * md;
        float R1 = v[k].y * md;
        float R2 = v[k].z * mr;
        r2 += R0 * R0 + R1 * R1 + R2 * R2;
    }

    for (int off = 16; off > 0; off >>= 1)
        r2 += __shfl_down_sync(0xffffffffu, r2, off);

    __shared__ float sr[8];
    int lane = tid & 31;
    int wid  = tid >> 5;
    if (lane == 0) sr[wid] = r2;
    __syncthreads();

    if (wid == 0) {
        float rr = (lane < 8) ? sr[lane] : 0.f;
        for (int off = 4; off > 0; off >>= 1)
            rr += __shfl_down_sync(0xffffffffu, rr, off);
        if (lane == 0) {
            atomicAdd(&g_acc[0], (double)rr);
            __threadfence();
            unsigned ticket = atomicAdd(&g_done, 1u);
            if (ticket == gridDim.x - 1) {
                double fn = g_acc[1];
                if (fn < 1e-30) fn = 1e-30;
                out[0] = (float)(g_acc[0] / fn);
                g_acc[0] = 0.0;
                g_acc[1] = 0.0;
                g_done = 0u;
            }
        }
    }
}

// ---------------------------------------------------------------------------
// Launch
// ---------------------------------------------------------------------------
extern "C" void kernel_launch(void* const* d_in, const int* in_sizes, int n_in,
                              void* d_out, int out_size)
{
    const float* pred_raw = (const float*)d_in[0];   // [N,3]
    const float* u_c      = (const float*)d_in[1];   // [1]
    const float* theta_c  = (const float*)d_in[2];   // [1]
    const float* elem_len = (const float*)d_in[3];   // [E]
    const float* prop_E   = (const float*)d_in[4];   // [E]
    const float* prop_A   = (const float*)d_in[5];   // [E]
    const float* prop_I   = (const float*)d_in[6];   // [E]
    const float* dirs     = (const float*)d_in[7];   // [E,3]
    const float* F_ext    = (const float*)d_in[8];   // [N,3]
    const float* bc_disp  = (const float*)d_in[9];   // [N,1]
    const float* bc_rot   = (const float*)d_in[10];  // [N,1]
    const int*   conn     = (const int*)d_in[11];    // [E,2]

    int N = in_sizes[0] / 3;
    int E = in_sizes[3];

    float* out = (float*)d_out;

    prep_kernel<<<(N + NPB - 1) / NPB, PTB>>>(
        (const float4*)pred_raw, (const float4*)F_ext,
        bc_disp, bc_rot, u_c, theta_c, N);

    elem_kernel<<<(E + EPB - 1) / EPB, ETB>>>(
        (const float4*)elem_len, (const float4*)prop_E,
        (const float4*)prop_A, (const float4*)prop_I,
        (const float4*)dirs, (const int4*)conn, E);

    int tail = E & 3;
    if (tail > 0) {
        elem_tail_kernel<<<1, 256>>>(elem_len, prop_E, prop_A, prop_I,
                                     dirs, conn, E & ~3, E);
    }

    node_kernel<<<(N + 2047) / 2048, 256>>>(out, N);
}